// round 16
// baseline (speedup 1.0000x reference)
#include <cuda_runtime.h>
#include <cuda_fp16.h>
#include <cstdint>

// ---------------------------------------------------------------------------
// SelfAttention block, sm_100 baseline target: tensor cores via mma.sync
// m16n8k16 fp16 (f32 accumulate), all MMAs single-term fp16; exp via
// ex2.approx.f16x2.
// R15: (1) attention kc-chunk restructured to overlap the S k-half-1 HMMAs
// with the k-half-0 exp MUFU ops (was: 16 HMMA -> 8 MUFU -> 16 HMMA fully
// serial per warp; now the MUFU tail is half-hidden behind tensor work).
// (2) linear_tc reverted to its best measured config (2-stage, 48KB,
// launch_bounds(128) -> regs ~126, 4 CTAs/SM).
// ---------------------------------------------------------------------------

#define SEQ   2048
#define DM    1024
#define HEADS 16
#define HD    64
#define NTOK  8192
#define BHN   64
#define BN    64             // kv tile rows
#define NT    (SEQ / BN)     // 32

// Q pre-scale: (1/sqrt(1024)) * log2(e).
#define QSCALE (1.4426950408889634f / 32.0f)

// ------------------------- device scratch ---------------------------------
__device__ unsigned short g_Q[BHN * SEQ * HD];          // fp16, pre-scaled
__device__ unsigned short g_K[BHN * SEQ * HD];          // fp16
__device__ unsigned short g_V[BHN * SEQ * HD];          // fp16
__device__ unsigned short g_O[(size_t)NTOK * DM];       // concat (fp16)
__device__ unsigned short g_W[DM * DM];                 // Wl fp16
__device__ float g_LIN[(size_t)NTOK * DM];

// ------------------------- helpers ----------------------------------------
__device__ __forceinline__ uint32_t smem_u32(const void* p) {
    uint32_t a;
    asm("{ .reg .u64 t; cvta.to.shared.u64 t, %1; cvt.u32.u64 %0, t; }"
        : "=r"(a) : "l"(p));
    return a;
}

// Pack two fp32 into f16x2 (lo = x0, hi = x1) — single cvt instruction.
__device__ __forceinline__ uint32_t pack2h(float x0, float x1) {
    uint32_t d;
    asm("cvt.rn.f16x2.f32 %0, %1, %2;" : "=r"(d) : "f"(x1), "f"(x0));
    return d;
}

// f16x2 exp2 (one MUFU op, two exps).
__device__ __forceinline__ uint32_t hex2(uint32_t x) {
    uint32_t d;
    asm("ex2.approx.f16x2 %0, %1;" : "=r"(d) : "r"(x));
    return d;
}

__device__ __forceinline__ uint32_t hadd2u(uint32_t a, uint32_t b) {
    uint32_t d;
    asm("add.rn.f16x2 %0, %1, %2;" : "=r"(d) : "r"(a), "r"(b));
    return d;
}

__device__ __forceinline__ float2 h22f2(uint32_t x) {
    __half2 h = *reinterpret_cast<__half2*>(&x);
    return __half22float2(h);
}

// Swizzled offset for 128B rows: row*128 + (colbyte ^ ((row&7)*16)).
__device__ __forceinline__ uint32_t swz(int row, int colbyte) {
    return (uint32_t)(row * 128 + (colbyte ^ ((row & 7) * 16)));
}

#define CP16(dst, src) \
    asm volatile("cp.async.cg.shared.global [%0], [%1], 16;" \
                 :: "r"((uint32_t)(dst)), "l"((const void*)(src)) : "memory")
#define CPCOMMIT() asm volatile("cp.async.commit_group;" ::: "memory")
#define CPWAIT(n)  asm volatile("cp.async.wait_group %0;" :: "n"(n) : "memory")

#define LDSM_X4(r0, r1, r2, r3, addr) \
    asm volatile("ldmatrix.sync.aligned.m8n8.x4.shared.b16 {%0,%1,%2,%3}, [%4];" \
                 : "=r"(r0), "=r"(r1), "=r"(r2), "=r"(r3) : "r"(addr))

#define LDSM_X4T(r0, r1, r2, r3, addr) \
    asm volatile("ldmatrix.sync.aligned.m8n8.x4.trans.shared.b16 {%0,%1,%2,%3}, [%4];" \
                 : "=r"(r0), "=r"(r1), "=r"(r2), "=r"(r3) : "r"(addr))

#define HMMA(d, a, b0, b1) \
    asm volatile("mma.sync.aligned.m16n8k16.row.col.f32.f16.f16.f32 " \
                 "{%0,%1,%2,%3},{%4,%5,%6,%7},{%8,%9},{%0,%1,%2,%3};" \
                 : "+f"((d)[0]), "+f"((d)[1]), "+f"((d)[2]), "+f"((d)[3]) \
                 : "r"((a)[0]), "r"((a)[1]), "r"((a)[2]), "r"((a)[3]), \
                   "r"(b0), "r"(b1))

// ---------------------------------------------------------------------------
// Kernel 1: QKV projection via HMMA.
// X viewed as [131072, 64] (row = token*16 + head). Y = X @ W^T.
// CTA = 128 rows (4 warps x 32 rows), W staged once in 8KB swizzled smem.
// ---------------------------------------------------------------------------
__global__ __launch_bounds__(128) void qkv_tc(
    const float* __restrict__ qin, const float* __restrict__ kin,
    const float* __restrict__ vin,
    const float* __restrict__ Wq, const float* __restrict__ Wk,
    const float* __restrict__ Wv)
{
    __shared__ __align__(16) unsigned short ws[64 * 64];   // 8KB, 128B rows
    const uint32_t sb = smem_u32(ws);

    const int which = blockIdx.y;
    const float* X = (which == 0) ? qin : (which == 1) ? kin : vin;
    const float* W = (which == 0) ? Wq  : (which == 1) ? Wk  : Wv;
    unsigned short* OUT = (which == 0) ? g_Q : (which == 1) ? g_K : g_V;

    const int tid = threadIdx.x, warp = tid >> 5, lane = tid & 31;
    const int g = lane >> 2, tq = lane & 3;
    const int rr = lane & 7, sel = lane >> 3;
    const int rbase = blockIdx.x * 128;

    // Stage W (fp32 -> fp16, swizzled): 512 16B-lines, 4 per thread.
    #pragma unroll
    for (int j = 0; j < 4; ++j) {
        int L = tid + 128 * j;
        int r = L >> 3, seg = L & 7;
        const float4* wr = (const float4*)(W + r * 64 + seg * 8);
        float4 w0 = wr[0], w1 = wr[1];
        uint4 v;
        v.x = pack2h(w0.x, w0.y);
        v.y = pack2h(w0.z, w0.w);
        v.z = pack2h(w1.x, w1.y);
        v.w = pack2h(w1.z, w1.w);
        *(uint4*)((char*)ws + swz(r, seg * 16)) = v;
    }
    __syncthreads();

    // A fragments: direct global fp32 loads + convert. 2 m-frags x 4 k-steps.
    uint32_t a[2][4][4];
    #pragma unroll
    for (int mt = 0; mt < 2; ++mt) {
        const size_t rA = (size_t)(rbase + warp * 32 + mt * 16 + g) * 64;
        const size_t rB = rA + 8 * 64;
        #pragma unroll
        for (int ks = 0; ks < 4; ++ks) {
            int cA = ks * 16 + 2 * tq, cB = cA + 8;
            float2 xA0 = *(const float2*)(X + rA + cA);
            float2 xB0 = *(const float2*)(X + rB + cA);
            float2 xA1 = *(const float2*)(X + rA + cB);
            float2 xB1 = *(const float2*)(X + rB + cB);
            a[mt][ks][0] = pack2h(xA0.x, xA0.y);
            a[mt][ks][1] = pack2h(xB0.x, xB0.y);
            a[mt][ks][2] = pack2h(xA1.x, xA1.y);
            a[mt][ks][3] = pack2h(xB1.x, xB1.y);
        }
    }

    float acc[2][8][4];
    #pragma unroll
    for (int mt = 0; mt < 2; ++mt)
        #pragma unroll
        for (int nt = 0; nt < 8; ++nt)
            #pragma unroll
            for (int j = 0; j < 4; ++j) acc[mt][nt][j] = 0.f;

    #pragma unroll
    for (int ks = 0; ks < 4; ++ks) {
        #pragma unroll
        for (int nt2 = 0; nt2 < 4; ++nt2) {
            uint32_t addr = sb + swz(nt2 * 16 + (sel >> 1) * 8 + rr,
                                     ks * 32 + (sel & 1) * 16);
            uint32_t b0, b1, b2, b3;
            LDSM_X4(b0, b1, b2, b3, addr);
            #pragma unroll
            for (int mt = 0; mt < 2; ++mt) {
                HMMA(acc[mt][nt2 * 2],     a[mt][ks], b0, b1);
                HMMA(acc[mt][nt2 * 2 + 1], a[mt][ks], b2, b3);
            }
        }
    }

    const float scale = (which == 0) ? QSCALE : 1.0f;
    #pragma unroll
    for (int mt = 0; mt < 2; ++mt) {
        int rA = rbase + warp * 32 + mt * 16 + g;
        int rB = rA + 8;
        int nA = rA >> 4, hA = rA & 15;
        int nB = rB >> 4, hB = rB & 15;
        size_t oA = (((size_t)(nA >> 11) * HEADS + hA) * SEQ + (nA & 2047)) * HD;
        size_t oB = (((size_t)(nB >> 11) * HEADS + hB) * SEQ + (nB & 2047)) * HD;
        #pragma unroll
        for (int nt = 0; nt < 8; ++nt) {
            int c = nt * 8 + 2 * tq;
            *(uint32_t*)(OUT + oA + c) =
                pack2h(acc[mt][nt][0] * scale, acc[mt][nt][1] * scale);
            *(uint32_t*)(OUT + oB + c) =
                pack2h(acc[mt][nt][2] * scale, acc[mt][nt][3] * scale);
        }
    }
}

// ---------------------------------------------------------------------------
// Kernel 2: round Wl to fp16.
// ---------------------------------------------------------------------------
__global__ __launch_bounds__(256) void split_wl_kernel(const float* __restrict__ W)
{
    int i = (blockIdx.x * 256 + threadIdx.x) * 4;
    float4 w = *(const float4*)(W + i);
    uint2 v = make_uint2(pack2h(w.x, w.y), pack2h(w.z, w.w));
    *(uint2*)(g_W + i) = v;
}

// ---------------------------------------------------------------------------
// Kernel 3: attention. 128 threads = 4 warps x 32 q-rows (2 m-frags).
// All single-term fp16 MMAs; exp via ex2.approx.f16x2.
// kc chunk pipelined: S(p=0) HMMAs -> exp(p=0) MUFU -> S(p=1) HMMAs
// (co-issue with MUFU) -> exp(p=1) -> PV.
// SMEM 32KB: K0@0 K1@8192 V0@16384 V1@24576. 3 CTAs/SM.
// ---------------------------------------------------------------------------
__device__ __forceinline__ void attn_load_tile(
    uint32_t dst, const unsigned short* P, int tid)
{
    #pragma unroll
    for (int j = 0; j < 4; ++j) {
        int L = tid + 128 * j;              // 0..511 lines of 16B
        int r = L >> 3, seg = L & 7;
        CP16(dst + swz(r, seg * 16), P + (size_t)r * HD + seg * 8);
    }
}

__global__ __launch_bounds__(128, 3) void attn_tc()
{
    extern __shared__ __align__(128) char smem[];
    const uint32_t sb = smem_u32(smem);
    const int tid = threadIdx.x, warp = tid >> 5, lane = tid & 31;
    const int qb = blockIdx.x, bh = blockIdx.y;
    const int g = lane >> 2, tq = lane & 3;
    const int q0 = qb * 128 + warp * 32;
    const int rr = lane & 7, sel = lane >> 3;

    const unsigned short* Kp = g_K + (size_t)bh * SEQ * HD;
    const unsigned short* Vp = g_V + (size_t)bh * SEQ * HD;

    attn_load_tile(sb,         Kp, tid);
    attn_load_tile(sb + 16384, Vp, tid);
    CPCOMMIT();
    attn_load_tile(sb + 8192,  Kp + BN * HD, tid);
    attn_load_tile(sb + 24576, Vp + BN * HD, tid);
    CPCOMMIT();

    // Q fragments resident in registers: 2 m-frags x 4 k-steps.
    uint32_t qh[2][4][4];
    #pragma unroll
    for (int mt = 0; mt < 2; ++mt) {
        const size_t rA = ((size_t)bh * SEQ + q0 + mt * 16 + g) * HD;
        const size_t rB = rA + 8 * HD;
        #pragma unroll
        for (int ks = 0; ks < 4; ++ks) {
            int cA = ks * 16 + 2 * tq, cB = cA + 8;
            qh[mt][ks][0] = *(const uint32_t*)(g_Q + rA + cA);
            qh[mt][ks][1] = *(const uint32_t*)(g_Q + rB + cA);
            qh[mt][ks][2] = *(const uint32_t*)(g_Q + rA + cB);
            qh[mt][ks][3] = *(const uint32_t*)(g_Q + rB + cB);
        }
    }

    float o[2][8][4];
    #pragma unroll
    for (int mt = 0; mt < 2; ++mt)
        #pragma unroll
        for (int e = 0; e < 8; ++e)
            #pragma unroll
            for (int j = 0; j < 4; ++j) o[mt][e][j] = 0.f;
    float lsum[2][2] = {{0.f, 0.f}, {0.f, 0.f}};

    for (int i = 0; i < NT; ++i) {
        if (i + 2 < NT) { CPWAIT(1); } else { CPWAIT(0); }
        __syncthreads();

        const uint32_t kb = sb + (i & 1) * 8192;
        const uint32_t vb = sb + 16384 + (i & 1) * 8192;

        #pragma unroll
        for (int kc = 0; kc < 4; ++kc) {
            float s[2][2][4];
            #pragma unroll
            for (int mt = 0; mt < 2; ++mt)
                #pragma unroll
                for (int p = 0; p < 2; ++p)
                    #pragma unroll
                    for (int j = 0; j < 4; ++j) s[mt][p][j] = 0.f;

            // ---- S, k-half 0 (kv rows kc*16..+7); save k-half-1 frags ----
            uint32_t b2s[4], b3s[4];
            #pragma unroll
            for (int ks = 0; ks < 4; ++ks) {
                uint32_t addr = kb + swz(kc * 16 + (sel >> 1) * 8 + rr,
                                         ks * 32 + (sel & 1) * 16);
                uint32_t b0, b1, b2, b3;
                LDSM_X4(b0, b1, b2, b3, addr);
                HMMA(s[0][0], qh[0][ks], b0, b1);
                HMMA(s[1][0], qh[1][ks], b0, b1);
                b2s[ks] = b2;
                b3s[ks] = b3;
            }

            // ---- exp(p=0): MUFU ops issued before the p=1 HMMA block so
            //      tensor and MUFU pipes co-execute ----
            uint32_t ph[2][4];
            ph[0][0] = hex2(pack2h(s[0][0][0], s[0][0][1]));
            ph[0][1] = hex2(pack2h(s[0][0][2], s[0][0][3]));
            ph[1][0] = hex2(pack2h(s[1][0][0], s[1][0][1]));
            ph[1][1] = hex2(pack2h(s[1][0][2], s[1][0][3]));

            // ---- S, k-half 1 (independent of the MUFU ops above) ----
            #pragma unroll
            for (int ks = 0; ks < 4; ++ks) {
                HMMA(s[0][1], qh[0][ks], b2s[ks], b3s[ks]);
                HMMA(s[1][1], qh[1][ks], b2s[ks], b3s[ks]);
            }

            // ---- exp(p=1) ----
            ph[0][2] = hex2(pack2h(s[0][1][0], s[0][1][1]));
            ph[0][3] = hex2(pack2h(s[0][1][2], s[0][1][3]));
            ph[1][2] = hex2(pack2h(s[1][1][0], s[1][1][1]));
            ph[1][3] = hex2(pack2h(s[1][1][2], s[1][1][3]));

            #pragma unroll
            for (int mt = 0; mt < 2; ++mt) {
                float2 fA = h22f2(hadd2u(ph[mt][0], ph[mt][2]));
                float2 fB = h22f2(hadd2u(ph[mt][1], ph[mt][3]));
                lsum[mt][0] += fA.x + fA.y;
                lsum[mt][1] += fB.x + fB.y;
            }

            // ---- O += P @ V for this kv chunk (1-term) ----
            #pragma unroll
            for (int et2 = 0; et2 < 4; ++et2) {
                uint32_t addr = vb + swz(kc * 16 + (sel & 1) * 8 + rr,
                                         (et2 * 2 + (sel >> 1)) * 16);
                uint32_t b0, b1, b2, b3;
                LDSM_X4T(b0, b1, b2, b3, addr);
                #pragma unroll
                for (int mt = 0; mt < 2; ++mt) {
                    HMMA(o[mt][et2 * 2],     ph[mt], b0, b1);
                    HMMA(o[mt][et2 * 2 + 1], ph[mt], b2, b3);
                }
            }
        }

        __syncthreads();
        if (i + 2 < NT) {
            size_t off = (size_t)(i + 2) * BN * HD;
            attn_load_tile(sb + (i & 1) * 8192,          Kp + off, tid);
            attn_load_tile(sb + 16384 + (i & 1) * 8192,  Vp + off, tid);
            CPCOMMIT();
        }
    }

    // ---- normalize + write concat (single fp16) ----
    const int b = bh >> 4, h = bh & 15;
    #pragma unroll
    for (int mt = 0; mt < 2; ++mt) {
        float l0 = lsum[mt][0], l1 = lsum[mt][1];
        l0 += __shfl_xor_sync(0xffffffffu, l0, 1);
        l0 += __shfl_xor_sync(0xffffffffu, l0, 2);
        l1 += __shfl_xor_sync(0xffffffffu, l1, 1);
        l1 += __shfl_xor_sync(0xffffffffu, l1, 2);
        const float i0 = 1.f / l0, i1 = 1.f / l1;

        const int t0 = q0 + mt * 16 + g;
        const size_t o0 = ((size_t)b * SEQ + t0) * DM + h * HD;
        const size_t o1 = o0 + (size_t)8 * DM;

        #pragma unroll
        for (int et = 0; et < 8; ++et) {
            int c = et * 8 + 2 * tq;
            *(uint32_t*)(g_O + o0 + c) = pack2h(o[mt][et][0] * i0,
                                                o[mt][et][1] * i0);
            *(uint32_t*)(g_O + o1 + c) = pack2h(o[mt][et][2] * i1,
                                                o[mt][et][3] * i1);
        }
    }
}

// ---------------------------------------------------------------------------
// Kernel 4: linear_tc — lin = concat @ Wl^T, single-term fp16.
// Best measured config (R10): 128 threads, tile 128x64, BK=64, 2 stages
// (24KB each -> 48KB), launch_bounds(128).
// ---------------------------------------------------------------------------
__global__ __launch_bounds__(128) void linear_tc()
{
    extern __shared__ __align__(128) char smem[];
    const uint32_t sb = smem_u32(smem);
    const int tid = threadIdx.x, warp = tid >> 5, lane = tid & 31;
    const int g = lane >> 2, tq = lane & 3;
    const int rr = lane & 7, sel = lane >> 3;
    const int rb = blockIdx.x * 128, cb = blockIdx.y * 64;

    auto load_chunk = [&](int kc) {
        uint32_t base = sb + (kc & 1) * 24576;
        #pragma unroll
        for (int j = 0; j < 8; ++j) {
            int L = tid + 128 * j;           // 0..1023: A rows
            int r = L >> 3, seg = L & 7;
            size_t ao = (size_t)(rb + r) * DM + kc * 64 + seg * 8;
            CP16(base + swz(r, seg * 16), g_O + ao);
        }
        #pragma unroll
        for (int j = 0; j < 4; ++j) {
            int L = tid + 128 * j;           // 0..511: B rows (64)
            int r = L >> 3, seg = L & 7;
            size_t bo = (size_t)(cb + r) * DM + kc * 64 + seg * 8;
            CP16(base + 16384 + swz(r, seg * 16), g_W + bo);
        }
        CPCOMMIT();
    };

    load_chunk(0);
    load_chunk(1);

    float acc[2][8][4];
    #pragma unroll
    for (int mt = 0; mt < 2; ++mt)
        #pragma unroll
        for (int nt = 0; nt < 8; ++nt)
            #pragma unroll
            for (int j = 0; j < 4; ++j) acc[mt][nt][j] = 0.f;

    for (int kc = 0; kc < 16; ++kc) {
        if (kc + 2 < 16) { CPWAIT(1); } else { CPWAIT(0); }
        __syncthreads();
        const uint32_t base = sb + (kc & 1) * 24576;

        #pragma unroll
        for (int ks = 0; ks < 4; ++ks) {
            uint32_t ah[2][4];
            #pragma unroll
            for (int mt = 0; mt < 2; ++mt) {
                uint32_t off = swz(warp * 32 + mt * 16 + (sel & 1) * 8 + rr,
                                   ks * 32 + (sel >> 1) * 16);
                LDSM_X4(ah[mt][0], ah[mt][1], ah[mt][2], ah[mt][3], base + off);
            }
            #pragma unroll
            for (int nt2 = 0; nt2 < 4; ++nt2) {
                uint32_t addr = base + 16384
                              + swz(nt2 * 16 + (sel >> 1) * 8 + rr,
                                    ks * 32 + (sel & 1) * 16);
                uint32_t b0, b1, b2, b3;
                LDSM_X4(b0, b1, b2, b3, addr);
                #pragma unroll
                for (int mt = 0; mt < 2; ++mt) {
                    HMMA(acc[mt][nt2 * 2],     ah[mt], b0, b1);
                    HMMA(acc[mt][nt2 * 2 + 1], ah[mt], b2, b3);
                }
            }
        }

        __syncthreads();
        if (kc + 2 < 16) load_chunk(kc + 2);
    }

    #pragma unroll
    for (int mt = 0; mt < 2; ++mt) {
        int r = rb + warp * 32 + mt * 16 + g;
        #pragma unroll
        for (int nt = 0; nt < 8; ++nt) {
            int c = cb + nt * 8 + 2 * tq;
            *(float2*)(g_LIN + (size_t)r * DM + c) =
                make_float2(acc[mt][nt][0], acc[mt][nt][1]);
            *(float2*)(g_LIN + (size_t)(r + 8) * DM + c) =
                make_float2(acc[mt][nt][2], acc[mt][nt][3]);
        }
    }
}

// ---------------------------------------------------------------------------
// Kernel 5: LayerNorm + residual.
// ---------------------------------------------------------------------------
__global__ __launch_bounds__(256) void ln_kernel(
    const float* __restrict__ qin, const float* __restrict__ gamma,
    const float* __restrict__ beta, float* __restrict__ out)
{
    const int row = blockIdx.x;
    const int tid = threadIdx.x;

    const float4 x = *(const float4*)(g_LIN + (size_t)row * DM + tid * 4);
    float s  = x.x + x.y + x.z + x.w;
    float ss = fmaf(x.x, x.x, fmaf(x.y, x.y, fmaf(x.z, x.z, x.w * x.w)));

    #pragma unroll
    for (int m = 16; m >= 1; m >>= 1) {
        s  += __shfl_xor_sync(0xffffffffu, s, m);
        ss += __shfl_xor_sync(0xffffffffu, ss, m);
    }

    __shared__ float rs[8], rss[8];
    __shared__ float sh_mean, sh_rstd;
    const int wid = tid >> 5, lane = tid & 31;
    if (lane == 0) { rs[wid] = s; rss[wid] = ss; }
    __syncthreads();
    if (tid == 0) {
        float S = 0.f, SS = 0.f;
        #pragma unroll
        for (int i = 0; i < 8; ++i) { S += rs[i]; SS += rss[i]; }
        float mean = S * (1.f / DM);
        float var  = SS * (1.f / DM) - mean * mean;
        sh_mean = mean;
        sh_rstd = rsqrtf(var + 1e-5f);
    }
    __syncthreads();

    const float mean = sh_mean, rstd = sh_rstd;
    const float4 g  = *(const float4*)(gamma + tid * 4);
    const float4 bt = *(const float4*)(beta + tid * 4);
    const float4 qv = *(const float4*)(qin + (size_t)row * DM + tid * 4);
    float4 o;
    o.x = qv.x + (x.x - mean) * rstd * g.x + bt.x;
    o.y = qv.y + (x.y - mean) * rstd * g.y + bt.y;
    o.z = qv.z + (x.z - mean) * rstd * g.z + bt.z;
    o.w = qv.w + (x.w - mean) * rstd * g.w + bt.w;
    *(float4*)(out + (size_t)row * DM + tid * 4) = o;
}

// ---------------------------------------------------------------------------
// Launch
// ---------------------------------------------------------------------------
extern "C" void kernel_launch(void* const* d_in, const int* in_sizes, int n_in,
                              void* d_out, int out_size)
{
    const float* q     = (const float*)d_in[0];
    const float* k     = (const float*)d_in[1];
    const float* v     = (const float*)d_in[2];
    const float* Wq    = (const float*)d_in[3];
    const float* Wk    = (const float*)d_in[4];
    const float* Wv    = (const float*)d_in[5];
    const float* Wl    = (const float*)d_in[6];
    const float* gamma = (const float*)d_in[7];
    const float* beta  = (const float*)d_in[8];

    const int attn_smem = 32768;
    const int lin_smem  = 49152;

    cudaFuncSetAttribute(attn_tc,
                         cudaFuncAttributeMaxDynamicSharedMemorySize, attn_smem);
    cudaFuncSetAttribute(linear_tc,
                         cudaFuncAttributeMaxDynamicSharedMemorySize, lin_smem);

    qkv_tc<<<dim3(1024, 3), 128>>>(q, k, v, Wq, Wk, Wv);
    split_wl_kernel<<<DM * DM / 1024, 256>>>(Wl);
    attn_tc<<<dim3(16, 64), 128, attn_smem>>>();
    linear_tc<<<dim3(64, 16), 128, lin_smem>>>();
    ln_kernel<<<NTOK, 256>>>(q, gamma, beta, (float*)d_out);
}